// round 14
// baseline (speedup 1.0000x reference)
#include <cuda_runtime.h>
#include <cuda_fp16.h>
#include <math.h>
#include <stdint.h>

#define MTOT 131072
#define TPB  256
#define TOK  128
#define NBLK (MTOT / TOK)

// word (uint32/half2) strides
#define XHS 68    // x|h tile row stride in words; %32==4 -> conflict-free scalar A loads
#define HBS 36    // alt h1 buffer row stride; %32==4 -> same conflict-free class
#define WS  40    // K=64 weight row stride in words; %32==8 -> LDS.64 conflict-free
#define FCS 72    // K=128 weight row stride in words

// smem word offsets
#define FCB_OFF   0        // 5184 words: FC weights (stage A), then h1-odd buffer [128][36]
#define RING_OFF  5184     // 3 x 3840 ring
#define RBSZ      3840
#define SXH_OFF   16704    // [128][68]
#define SGATE_OFF 25408    // [128][9] f32
#define SMEMW     26560    // 106,240 B -> 2 CTAs/SM

// packed-weight global offsets (words)
#define GW_FC   0          // [72][72] fc(64)+gate(8), K=128
#define GW_GRU  5184       // 4 chunks x 3840 (ih @ +0, hh @ +1920)
#define GW_E    20544      // 8 experts x 3840 (E1 @ +0, E2 @ +2560)
#define GW_TOT  51264

__device__ __align__(16) uint32_t g_wp[GW_TOT];

__device__ __forceinline__ uint32_t h2u(float a, float b) {
    __half2 h = __floats2half2_rn(a, b);
    return *reinterpret_cast<uint32_t*>(&h);
}
__device__ __forceinline__ float2 u2f2(uint32_t u) {
    __half2 h = *reinterpret_cast<__half2*>(&u);
    return __half22float2(h);
}
__device__ __forceinline__ float tanh_f(float v) {
    float y; asm("tanh.approx.f32 %0, %1;" : "=f"(y) : "f"(v)); return y;
}
__device__ __forceinline__ float sig_(float v) {
    return fmaf(tanh_f(0.5f * v), 0.5f, 0.5f);
}
__device__ __forceinline__ int wp_(int w) {
    return ((w >> 3) << 3) + ((w & 3) << 1) + ((w >> 2) & 1);
}

__device__ __forceinline__ void cp16w(uint32_t* dst, const uint32_t* src) {
    uint32_t d = (uint32_t)__cvta_generic_to_shared(dst);
    asm volatile("cp.async.cg.shared.global [%0], [%1], 16;" :: "r"(d), "l"(src));
}
__device__ __forceinline__ void stage_async(uint32_t* dst, const uint32_t* src, int n, int t) {
    for (int i = t * 4; i < n; i += TPB * 4) cp16w(dst + i, src + i);
}
#define CP_COMMIT asm volatile("cp.async.commit_group;")
#define CP_WAIT0  asm volatile("cp.async.wait_group 0;")
#define CP_WAIT1  asm volatile("cp.async.wait_group 1;")
#define PAIR_BAR  asm volatile("bar.sync %0, 64;" :: "r"(p + 1) : "memory")

__device__ __forceinline__ void mma16(float* d,
    uint32_t a0, uint32_t a1, uint32_t a2, uint32_t a3, uint32_t b0, uint32_t b1)
{
    asm volatile(
        "mma.sync.aligned.m16n8k16.row.col.f32.f16.f16.f32 "
        "{%0,%1,%2,%3}, {%4,%5,%6,%7}, {%8,%9}, {%0,%1,%2,%3};"
        : "+f"(d[0]), "+f"(d[1]), "+f"(d[2]), "+f"(d[3])
        : "r"(a0), "r"(a1), "r"(a2), "r"(a3), "r"(b0), "r"(b1));
}

// scalar A-fragments for two m16 stripes, parametric stride
#define LOAD_A8S(ptr, stride)                         \
    uint32_t a0 = (ptr)[tig];                         \
    uint32_t a2 = (ptr)[tig + 4];                     \
    uint32_t a1 = (ptr)[8 * (stride) + tig];          \
    uint32_t a3 = (ptr)[8 * (stride) + tig + 4];      \
    uint32_t a4 = (ptr)[16 * (stride) + tig];         \
    uint32_t a6 = (ptr)[16 * (stride) + tig + 4];     \
    uint32_t a5 = (ptr)[24 * (stride) + tig];         \
    uint32_t a7 = (ptr)[24 * (stride) + tig + 4];

#define MMA2(acc, bv)                                       \
    mma16((acc)[0], a0, a1, a2, a3, (bv).x, (bv).y);        \
    mma16((acc)[1], a4, a5, a6, a7, (bv).x, (bv).y);

// ---------------- prep: pack + fp16-convert all weights once ----------------
__global__ void prep_pack(const float* __restrict__ fc_w, const float* __restrict__ gate_w,
                          const float* __restrict__ w_ih, const float* __restrict__ w_hh,
                          const float* __restrict__ e_w1, const float* __restrict__ e_w2)
{
    int tid = blockIdx.x * blockDim.x + threadIdx.x;
    int nth = gridDim.x * blockDim.x;
    for (int i = tid; i < 72 * 64; i += nth) {
        int j = i >> 6, w = i & 63;
        const float* src = (j < 64) ? (fc_w + j * 128) : (gate_w + (j - 64) * 128);
        g_wp[GW_FC + j * FCS + wp_(w)] = h2u(src[2 * w], src[2 * w + 1]);
    }
    for (int i = tid; i < 192 * 32; i += nth) {
        int R = i >> 5, w = i & 31;
        int c = (R & 63) >> 4, grp = R >> 6, lr = grp * 16 + (R & 15);
        int d = GW_GRU + c * 3840 + lr * WS + wp_(w);
        g_wp[d]        = h2u(w_ih[R * 64 + 2 * w], w_ih[R * 64 + 2 * w + 1]);
        g_wp[d + 1920] = h2u(w_hh[R * 64 + 2 * w], w_hh[R * 64 + 2 * w + 1]);
    }
    for (int i = tid; i < 8 * 64 * 32; i += nth) {
        int n = i >> 11, r = (i >> 5) & 63, w = i & 31;
        const float* src = e_w1 + n * 4096 + r * 64;
        g_wp[GW_E + n * 3840 + r * WS + wp_(w)] = h2u(src[2 * w], src[2 * w + 1]);
    }
    for (int i = tid; i < 8 * 32 * 32; i += nth) {
        int n = i >> 10, r = (i >> 5) & 31, w = i & 31;
        const float* src = e_w2 + n * 2048 + r * 64;
        g_wp[GW_E + n * 3840 + 2560 + r * WS + wp_(w)] = h2u(src[2 * w], src[2 * w + 1]);
    }
}

// ---------------- main: 8 warps, paired stripes, expert-level pipelining ----------------
__global__ void __launch_bounds__(TPB, 2) msp_main(
    const float* __restrict__ xin,  const float* __restrict__ hin,
    const float* __restrict__ fc_b,
    const float* __restrict__ b_ih, const float* __restrict__ b_hh,
    const float* __restrict__ e_b1, const float* __restrict__ e_b2,
    const float* __restrict__ gate_b,
    float* __restrict__ out)
{
    extern __shared__ uint32_t smw[];
    uint32_t* s_fc  = smw + FCB_OFF;    // FC weights, later h1-odd buffer
    uint32_t* s_xh  = smw + SXH_OFF;    // words 0..31 = x / h1-even; 32..63 = h_in/h
    float* s_gate   = (float*)(smw + SGATE_OFF);
    #define RING(i) (smw + RING_OFF + (i) * RBSZ)

    const int t = threadIdx.x, lane = t & 31, wid = t >> 5;
    const int gid = lane >> 2, tig = lane & 3;
    const int p = wid >> 1, half = wid & 1;
    const int r0 = p << 5, base = blockIdx.x * TOK;
    const int row0 = r0 + gid;

    // ---- prologue ----
    stage_async(s_fc, g_wp + GW_FC, 5184, t);
    stage_async(RING(0), g_wp + GW_GRU, 3840, t);
    CP_COMMIT;
    stage_async(RING(1), g_wp + GW_GRU + 3840, 3840, t);
    CP_COMMIT;
    {
        const float4* hsrc = (const float4*)hin;
        for (int i = t; i < TOK * 16; i += TPB) {
            int r = i >> 4, c = i & 15;
            float4 v = hsrc[(size_t)(base + r) * 16 + c];
            *(uint2*)(s_xh + r * XHS + 32 + 2 * c) = make_uint2(h2u(v.x, v.y), h2u(v.z, v.w));
        }
        const float4* xsrc = (const float4*)xin;
        for (int i = t; i < TOK * 16; i += TPB) {
            int r = i >> 4, c = i & 15;
            float4 v = xsrc[(size_t)(base + r) * 32 + c];
            *(uint2*)(s_xh + r * XHS + 2 * c) = make_uint2(h2u(v.x, v.y), h2u(v.z, v.w));
        }
    }
    CP_WAIT1;
    __syncthreads();

    // ---- Stage A ----
    {
        float accF[4][2][4], accG[2][4];
        #pragma unroll
        for (int nt = 0; nt < 4; ++nt) {
            int cb = half * 32 + nt * 8 + 2 * tig;
            float b0 = __ldg(fc_b + cb), b1 = __ldg(fc_b + cb + 1);
            #pragma unroll
            for (int s = 0; s < 2; ++s) {
                accF[nt][s][0] = b0; accF[nt][s][1] = b1;
                accF[nt][s][2] = b0; accF[nt][s][3] = b1;
            }
        }
        {
            float g0 = __ldg(gate_b + 2 * tig), g1 = __ldg(gate_b + 2 * tig + 1);
            #pragma unroll
            for (int s = 0; s < 2; ++s) {
                accG[s][0] = g0; accG[s][1] = g1; accG[s][2] = g0; accG[s][3] = g1;
            }
        }
        #pragma unroll
        for (int kh = 0; kh < 2; ++kh) {
            if (kh == 1) {
                __syncthreads();
                const float4* xsrc = (const float4*)xin;
                for (int i = t; i < TOK * 16; i += TPB) {
                    int r = i >> 4, c = i & 15;
                    float4 v = xsrc[(size_t)(base + r) * 32 + 16 + c];
                    *(uint2*)(s_xh + r * XHS + 2 * c) = make_uint2(h2u(v.x, v.y), h2u(v.z, v.w));
                }
                __syncthreads();
            }
            #pragma unroll
            for (int ks = 0; ks < 4; ++ks) {
                LOAD_A8S(s_xh + row0 * XHS + ks * 8, XHS)
                const int kb = (kh * 4 + ks) * 8 + 2 * tig;
                #pragma unroll
                for (int nt = 0; nt < 4; ++nt) {
                    uint2 bv = *(const uint2*)(s_fc + (half * 32 + nt * 8 + gid) * FCS + kb);
                    MMA2(accF[nt], bv)
                }
                if (half) {
                    uint2 gv = *(const uint2*)(s_fc + (64 + gid) * FCS + kb);
                    MMA2(accG, gv)
                }
            }
        }
        PAIR_BAR;
        #pragma unroll
        for (int nt = 0; nt < 4; ++nt) {
            int wq = half * 16 + nt * 4 + tig;
            #pragma unroll
            for (int s = 0; s < 2; ++s) {
                int ra = row0 + s * 16, rb = ra + 8;
                s_xh[ra * XHS + wq] = h2u(fmaxf(accF[nt][s][0], 0.f), fmaxf(accF[nt][s][1], 0.f));
                s_xh[rb * XHS + wq] = h2u(fmaxf(accF[nt][s][2], 0.f), fmaxf(accF[nt][s][3], 0.f));
            }
        }
        if (half) {
            #pragma unroll
            for (int s = 0; s < 2; ++s) {
                int ra = row0 + s * 16, rb = ra + 8;
                s_gate[ra * 9 + 2 * tig]     = sig_(accG[s][0]);
                s_gate[ra * 9 + 2 * tig + 1] = sig_(accG[s][1]);
                s_gate[rb * 9 + 2 * tig]     = sig_(accG[s][2]);
                s_gate[rb * 9 + 2 * tig + 1] = sig_(accG[s][3]);
            }
        }
    }

    // ---- GRU: 4 ring stages (R13 skeleton, scalar A-loads) ----
    float hpark[24];
    #pragma unroll 1
    for (int c = 0; c < 4; ++c) {
        CP_WAIT1;
        __syncthreads();
        {
            int s2 = c + 2;
            if (s2 < 4) stage_async(RING(s2 % 3), g_wp + GW_GRU + s2 * 3840, 3840, t);
            else        stage_async(RING(s2 % 3), g_wp + GW_E + (s2 - 4) * 3840, 3840, t);
            CP_COMMIT;
        }
        uint32_t* cur = RING(c % 3);

        float ar[2][4], az[2][4], ani[2][4], anh[2][4];
        {
            int j0 = c * 16 + half * 8 + 2 * tig;
            float v0 = __ldg(b_ih + j0) + __ldg(b_hh + j0);
            float v1 = __ldg(b_ih + j0 + 1) + __ldg(b_hh + j0 + 1);
            float z0 = __ldg(b_ih + 64 + j0) + __ldg(b_hh + 64 + j0);
            float z1 = __ldg(b_ih + 64 + j0 + 1) + __ldg(b_hh + 64 + j0 + 1);
            float n0 = __ldg(b_ih + 128 + j0), n1 = __ldg(b_ih + 128 + j0 + 1);
            float m0 = __ldg(b_hh + 128 + j0), m1 = __ldg(b_hh + 128 + j0 + 1);
            #pragma unroll
            for (int s = 0; s < 2; ++s) {
                ar[s][0] = v0; ar[s][1] = v1; ar[s][2] = v0; ar[s][3] = v1;
                az[s][0] = z0; az[s][1] = z1; az[s][2] = z0; az[s][3] = z1;
                ani[s][0] = n0; ani[s][1] = n1; ani[s][2] = n0; ani[s][3] = n1;
                anh[s][0] = m0; anh[s][1] = m1; anh[s][2] = m0; anh[s][3] = m1;
            }
        }
        #pragma unroll
        for (int ks = 0; ks < 4; ++ks) {           // x-part
            LOAD_A8S(s_xh + row0 * XHS + ks * 8, XHS)
            const int kb = ks * 8 + 2 * tig;
            uint2 br = *(const uint2*)(cur + (half * 8 + gid) * WS + kb);
            MMA2(ar, br)
            uint2 bz = *(const uint2*)(cur + (16 + half * 8 + gid) * WS + kb);
            MMA2(az, bz)
            uint2 bn = *(const uint2*)(cur + (32 + half * 8 + gid) * WS + kb);
            MMA2(ani, bn)
        }
        #pragma unroll
        for (int ks = 0; ks < 4; ++ks) {           // h-part
            LOAD_A8S(s_xh + row0 * XHS + 32 + ks * 8, XHS)
            const int kb = ks * 8 + 2 * tig;
            uint2 br = *(const uint2*)(cur + 1920 + (half * 8 + gid) * WS + kb);
            MMA2(ar, br)
            uint2 bz = *(const uint2*)(cur + 1920 + (16 + half * 8 + gid) * WS + kb);
            MMA2(az, bz)
            uint2 bn = *(const uint2*)(cur + 1920 + (32 + half * 8 + gid) * WS + kb);
            MMA2(anh, bn)
        }
        if (c == 3) { PAIR_BAR; }
        #pragma unroll
        for (int s = 0; s < 2; ++s) {
            #pragma unroll
            for (int rb_ = 0; rb_ < 2; ++rb_) {
                int row = row0 + s * 16 + rb_ * 8;
                int j = c * 16 + half * 8 + 2 * tig;
                int e0 = rb_ * 2;
                float2 hp = u2f2(s_xh[row * XHS + 32 + (j >> 1)]);
                float r0_ = sig_(ar[s][e0]),     r1_ = sig_(ar[s][e0 + 1]);
                float z0_ = sig_(az[s][e0]),     z1_ = sig_(az[s][e0 + 1]);
                float n0_ = tanh_f(fmaf(r0_, anh[s][e0],     ani[s][e0]));
                float n1_ = tanh_f(fmaf(r1_, anh[s][e0 + 1], ani[s][e0 + 1]));
                float h0_ = fmaf(z0_, hp.x - n0_, n0_);
                float h1_ = fmaf(z1_, hp.y - n1_, n1_);
                if (c < 3) { hpark[c * 8 + s * 4 + e0] = h0_; hpark[c * 8 + s * 4 + e0 + 1] = h1_; }
                else s_xh[row * XHS + 32 + (j >> 1)] = h2u(h0_, h1_);
            }
        }
        if (c == 3) {
            #pragma unroll
            for (int cc = 0; cc < 3; ++cc)
                #pragma unroll
                for (int s = 0; s < 2; ++s)
                    #pragma unroll
                    for (int rb_ = 0; rb_ < 2; ++rb_) {
                        int row = row0 + s * 16 + rb_ * 8;
                        int j = cc * 16 + half * 8 + 2 * tig;
                        s_xh[row * XHS + 32 + (j >> 1)] =
                            h2u(hpark[cc * 8 + s * 4 + rb_ * 2],
                                hpark[cc * 8 + s * 4 + rb_ * 2 + 1]);
                    }
        }
    }
    CP_WAIT1;          // E(0) complete (E(1) may be in flight)
    __syncthreads();   // GRU h writes visible block-wide; ring reads done

    // ---- h output ----
    {
        float4* hout = (float4*)(out + (size_t)MTOT * 32);
        for (int i = t; i < TOK * 16; i += TPB) {
            int r = i >> 4, c = i & 15;
            uint2 w2 = *(const uint2*)(s_xh + r * XHS + 32 + 2 * c);
            float2 f0 = u2f2(w2.x), f1 = u2f2(w2.y);
            hout[(size_t)(base + r) * 16 + c] = make_float4(f0.x, f0.y, f1.x, f1.y);
        }
    }

    // ---- standalone E1(0) -> accA (weights in RING(1)) ----
    float accA[4][2][4];
    #pragma unroll
    for (int nt = 0; nt < 4; ++nt) {
        int cb = half * 32 + nt * 8 + 2 * tig;
        float b0 = __ldg(e_b1 + cb), b1 = __ldg(e_b1 + cb + 1);
        #pragma unroll
        for (int s = 0; s < 2; ++s) {
            accA[nt][s][0] = b0; accA[nt][s][1] = b1;
            accA[nt][s][2] = b0; accA[nt][s][3] = b1;
        }
    }
    #pragma unroll
    for (int ks = 0; ks < 4; ++ks) {
        LOAD_A8S(s_xh + row0 * XHS + 32 + ks * 8, XHS)
        const int kb = ks * 8 + 2 * tig;
        #pragma unroll
        for (int nt = 0; nt < 4; ++nt) {
            uint2 bv = *(const uint2*)(RING(1) + (half * 32 + nt * 8 + gid) * WS + kb);
            MMA2(accA[nt], bv)
        }
    }

    // ---- expert segments: E2(n) interleaved with E1(n+1) ----
    float fq[2][2][4];
    #pragma unroll
    for (int q = 0; q < 2; ++q)
        #pragma unroll
        for (int s = 0; s < 2; ++s)
            { fq[q][s][0] = fq[q][s][1] = fq[q][s][2] = fq[q][s][3] = 0.f; }
    float* eobase = out + (size_t)MTOT * 96;

    #pragma unroll 1
    for (int n = 0; n < 8; ++n) {
        CP_WAIT0;          // E(n+1) weights complete
        __syncthreads();   // ring reuse safety
        if (n < 6) {
            stage_async(RING((6 + n) % 3), g_wp + GW_E + (n + 2) * 3840, 3840, t);
            CP_COMMIT;
        }
        uint32_t* curW = RING((4 + n) % 3);       // expert n   (E2 @ +2560)
        uint32_t* nxtW = RING((5 + n) % 3);       // expert n+1 (E1 @ +0)
        uint32_t* h1b  = (n & 1) ? s_fc : s_xh;   // h1 slot for expert n
        const int h1s  = (n & 1) ? HBS : XHS;

        // epilogue E1(n): relu(accA) fp16 -> h1b (pair-local rows)
        #pragma unroll
        for (int nt = 0; nt < 4; ++nt) {
            int wq = half * 16 + nt * 4 + tig;
            #pragma unroll
            for (int s = 0; s < 2; ++s) {
                int ra = row0 + s * 16, rb = ra + 8;
                h1b[ra * h1s + wq] = h2u(fmaxf(accA[nt][s][0], 0.f), fmaxf(accA[nt][s][1], 0.f));
                h1b[rb * h1s + wq] = h2u(fmaxf(accA[nt][s][2], 0.f), fmaxf(accA[nt][s][3], 0.f));
            }
        }
        PAIR_BAR;   // pair-local h1 handoff

        float accN[4][2][4];
        if (n < 7) {
            #pragma unroll
            for (int nt = 0; nt < 4; ++nt) {
                int cb = (n + 1) * 64 + half * 32 + nt * 8 + 2 * tig;
                float b0 = __ldg(e_b1 + cb), b1 = __ldg(e_b1 + cb + 1);
                #pragma unroll
                for (int s = 0; s < 2; ++s) {
                    accN[nt][s][0] = b0; accN[nt][s][1] = b1;
                    accN[nt][s][2] = b0; accN[nt][s][3] = b1;
                }
            }
        }
        float acc2[2][2][4];
        #pragma unroll
        for (int nt = 0; nt < 2; ++nt) {
            int cb = n * 32 + half * 16 + nt * 8 + 2 * tig;
            float b0 = __ldg(e_b2 + cb), b1 = __ldg(e_b2 + cb + 1);
            #pragma unroll
            for (int s = 0; s < 2; ++s) {
                acc2[nt][s][0] = b0; acc2[nt][s][1] = b1;
                acc2[nt][s][2] = b0; acc2[nt][s][3] = b1;
            }
        }
        // interleaved: E2(n) from h1b + E1(n+1) from h — two independent streams
        #pragma unroll
        for (int ks = 0; ks < 4; ++ks) {
            const int kb = ks * 8 + 2 * tig;
            {   // E2(n)
                LOAD_A8S(h1b + row0 * h1s + ks * 8, h1s)
                #pragma unroll
                for (int nt = 0; nt < 2; ++nt) {
                    uint2 bv = *(const uint2*)(curW + 2560 + (half * 16 + nt * 8 + gid) * WS + kb);
                    MMA2(acc2[nt], bv)
                }
            }
            if (n < 7) {   // E1(n+1)
                LOAD_A8S(s_xh + row0 * XHS + 32 + ks * 8, XHS)
                #pragma unroll
                for (int nt = 0; nt < 4; ++nt) {
                    uint2 bv = *(const uint2*)(nxtW + (half * 32 + nt * 8 + gid) * WS + kb);
                    MMA2(accN[nt], bv)
                }
            }
        }
        // E2 epilogue: gated accumulate + experts_out store
        #pragma unroll
        for (int s = 0; s < 2; ++s) {
            int ra = row0 + s * 16, rb = ra + 8;
            float w0 = s_gate[ra * 9 + n], w1 = s_gate[rb * 9 + n];
            #pragma unroll
            for (int nt = 0; nt < 2; ++nt) {
                fq[nt][s][0] = fmaf(acc2[nt][s][0], w0, fq[nt][s][0]);
                fq[nt][s][1] = fmaf(acc2[nt][s][1], w0, fq[nt][s][1]);
                fq[nt][s][2] = fmaf(acc2[nt][s][2], w1, fq[nt][s][2]);
                fq[nt][s][3] = fmaf(acc2[nt][s][3], w1, fq[nt][s][3]);
                int c0 = n * 32 + half * 16 + nt * 8 + 2 * tig;
                *(float2*)(eobase + (size_t)(base + ra) * 256 + c0) =
                    make_float2(acc2[nt][s][0], acc2[nt][s][1]);
                *(float2*)(eobase + (size_t)(base + rb) * 256 + c0) =
                    make_float2(acc2[nt][s][2], acc2[nt][s][3]);
            }
        }
        if (n < 7) {   // accA <- accN
            #pragma unroll
            for (int nt = 0; nt < 4; ++nt)
                #pragma unroll
                for (int s = 0; s < 2; ++s)
                    #pragma unroll
                    for (int e = 0; e < 4; ++e)
                        accA[nt][s][e] = accN[nt][s][e];
        }
    }

    // ---- final_q ----
    #pragma unroll
    for (int s = 0; s < 2; ++s) {
        int ra = row0 + s * 16, rb = ra + 8;
        #pragma unroll
        for (int nt = 0; nt < 2; ++nt) {
            int c0 = half * 16 + nt * 8 + 2 * tig;
            *(float2*)(out + (size_t)(base + ra) * 32 + c0) =
                make_float2(fq[nt][s][0] * 0.125f, fq[nt][s][1] * 0.125f);
            *(float2*)(out + (size_t)(base + rb) * 32 + c0) =
                make_float2(fq[nt][s][2] * 0.125f, fq[nt][s][3] * 0.125f);
        }
    }
}

extern "C" void kernel_launch(void* const* d_in, const int* in_sizes, int n_in,
                              void* d_out, int out_size) {
    (void)in_sizes; (void)n_in; (void)out_size;
    prep_pack<<<128, 256>>>(
        (const float*)d_in[2],  (const float*)d_in[12],
        (const float*)d_in[4],  (const float*)d_in[5],
        (const float*)d_in[8],  (const float*)d_in[10]);
    cudaFuncSetAttribute(msp_main, cudaFuncAttributeMaxDynamicSharedMemorySize, SMEMW * 4);
    msp_main<<<NBLK, TPB, SMEMW * 4>>>(
        (const float*)d_in[0],  (const float*)d_in[1],
        (const float*)d_in[3],
        (const float*)d_in[6],  (const float*)d_in[7],
        (const float*)d_in[9],  (const float*)d_in[11],
        (const float*)d_in[13],
        (float*)d_out);
}

// round 15
// speedup vs baseline: 1.1392x; 1.1392x over previous
#include <cuda_runtime.h>
#include <cuda_fp16.h>
#include <math.h>
#include <stdint.h>

#define MTOT 131072
#define TPB  128
#define TOK  64
#define NBLK (MTOT / TOK)

// word (uint32/half2) strides
#define XHS 68    // x|h tile row stride in words; %32==4 -> conflict-free scalar A loads
#define WS  40    // K=64 weight row stride in words; %32==8 -> LDS.64 conflict-free
#define FCS 72    // K=128 weight row stride in words

// smem word offsets
#define SW_OFF    0        // buf0 = 5184 words (FC + staged), buf1 = 3840
#define BUF1      5184
#define SXH_OFF   9024     // [64][68]
#define SGATE_OFF 13376    // [64][9] f32
#define SMEMW     13952    // 55,808 B -> 4 CTAs/SM (223.2 KB)

// packed-weight global offsets (words)
#define GW_FC   0          // [72][72] fc(64)+gate(8), K=128
#define GW_GRU  5184       // 4 chunks x 3840 (ih @ +0, hh @ +1920)
#define GW_E    20544      // 8 experts x 3840 (E1 @ +0, E2 @ +2560)
#define GW_TOT  51264

__device__ __align__(16) uint32_t g_wp[GW_TOT];

__device__ __forceinline__ uint32_t h2u(float a, float b) {
    __half2 h = __floats2half2_rn(a, b);
    return *reinterpret_cast<uint32_t*>(&h);
}
__device__ __forceinline__ float2 u2f2(uint32_t u) {
    __half2 h = *reinterpret_cast<__half2*>(&u);
    return __half22float2(h);
}
__device__ __forceinline__ float tanh_f(float v) {
    float y; asm("tanh.approx.f32 %0, %1;" : "=f"(y) : "f"(v)); return y;
}
__device__ __forceinline__ float sig_(float v) {
    return fmaf(tanh_f(0.5f * v), 0.5f, 0.5f);
}
__device__ __forceinline__ int wp_(int w) {
    return ((w >> 3) << 3) + ((w & 3) << 1) + ((w >> 2) & 1);
}

__device__ __forceinline__ void cp16w(uint32_t* dst, const uint32_t* src) {
    uint32_t d = (uint32_t)__cvta_generic_to_shared(dst);
    asm volatile("cp.async.cg.shared.global [%0], [%1], 16;" :: "r"(d), "l"(src));
}
__device__ __forceinline__ void stage_async(uint32_t* dst, const uint32_t* src, int n, int t) {
    for (int i = t * 4; i < n; i += TPB * 4) cp16w(dst + i, src + i);
}
#define CP_COMMIT asm volatile("cp.async.commit_group;")
#define CP_WAIT0  asm volatile("cp.async.wait_group 0;")
#define PAIR_BAR  asm volatile("bar.sync %0, 64;" :: "r"(p + 1) : "memory")

// fp16 m16n8k16, fp32 accumulate
__device__ __forceinline__ void mma16(float* d,
    uint32_t a0, uint32_t a1, uint32_t a2, uint32_t a3, uint32_t b0, uint32_t b1)
{
    asm volatile(
        "mma.sync.aligned.m16n8k16.row.col.f32.f16.f16.f32 "
        "{%0,%1,%2,%3}, {%4,%5,%6,%7}, {%8,%9}, {%0,%1,%2,%3};"
        : "+f"(d[0]), "+f"(d[1]), "+f"(d[2]), "+f"(d[3])
        : "r"(a0), "r"(a1), "r"(a2), "r"(a3), "r"(b0), "r"(b1));
}

#define LOAD_A8(ptr)                              \
    uint32_t a0 = (ptr)[tig];                     \
    uint32_t a2 = (ptr)[tig + 4];                 \
    uint32_t a1 = (ptr)[8 * XHS + tig];           \
    uint32_t a3 = (ptr)[8 * XHS + tig + 4];       \
    uint32_t a4 = (ptr)[16 * XHS + tig];          \
    uint32_t a6 = (ptr)[16 * XHS + tig + 4];      \
    uint32_t a5 = (ptr)[24 * XHS + tig];          \
    uint32_t a7 = (ptr)[24 * XHS + tig + 4];

#define MMA2(acc, bv)                                       \
    mma16((acc)[0], a0, a1, a2, a3, (bv).x, (bv).y);        \
    mma16((acc)[1], a4, a5, a6, a7, (bv).x, (bv).y);

// ---------------- prep: pack + fp16-convert all weights once ----------------
__global__ void prep_pack(const float* __restrict__ fc_w, const float* __restrict__ gate_w,
                          const float* __restrict__ w_ih, const float* __restrict__ w_hh,
                          const float* __restrict__ e_w1, const float* __restrict__ e_w2)
{
    int tid = blockIdx.x * blockDim.x + threadIdx.x;
    int nth = gridDim.x * blockDim.x;
    for (int i = tid; i < 72 * 64; i += nth) {
        int j = i >> 6, w = i & 63;
        const float* src = (j < 64) ? (fc_w + j * 128) : (gate_w + (j - 64) * 128);
        g_wp[GW_FC + j * FCS + wp_(w)] = h2u(src[2 * w], src[2 * w + 1]);
    }
    for (int i = tid; i < 192 * 32; i += nth) {
        int R = i >> 5, w = i & 31;
        int c = (R & 63) >> 4, grp = R >> 6, lr = grp * 16 + (R & 15);
        int d = GW_GRU + c * 3840 + lr * WS + wp_(w);
        g_wp[d]        = h2u(w_ih[R * 64 + 2 * w], w_ih[R * 64 + 2 * w + 1]);
        g_wp[d + 1920] = h2u(w_hh[R * 64 + 2 * w], w_hh[R * 64 + 2 * w + 1]);
    }
    for (int i = tid; i < 8 * 64 * 32; i += nth) {
        int n = i >> 11, r = (i >> 5) & 63, w = i & 31;
        const float* src = e_w1 + n * 4096 + r * 64;
        g_wp[GW_E + n * 3840 + r * WS + wp_(w)] = h2u(src[2 * w], src[2 * w + 1]);
    }
    for (int i = tid; i < 8 * 32 * 32; i += nth) {
        int n = i >> 10, r = (i >> 5) & 31, w = i & 31;
        const float* src = e_w2 + n * 2048 + r * 64;
        g_wp[GW_E + n * 3840 + 2560 + r * WS + wp_(w)] = h2u(src[2 * w], src[2 * w + 1]);
    }
}

// ---------------- main: 4 warps (2 pairs), 64 tokens/CTA, 4 CTAs/SM ----------------
__global__ void __launch_bounds__(TPB, 4) msp_main(
    const float* __restrict__ xin,  const float* __restrict__ hin,
    const float* __restrict__ fc_b,
    const float* __restrict__ b_ih, const float* __restrict__ b_hh,
    const float* __restrict__ e_b1, const float* __restrict__ e_b2,
    const float* __restrict__ gate_b,
    float* __restrict__ out)
{
    extern __shared__ uint32_t smw[];
    uint32_t* s_w  = smw + SW_OFF;
    uint32_t* s_xh = smw + SXH_OFF;   // per row: words 0..31 = x/h1, 32..63 = h_in/h
    float* s_gate  = (float*)(smw + SGATE_OFF);

    const int t = threadIdx.x, lane = t & 31, wid = t >> 5;
    const int gid = lane >> 2, tig = lane & 3;
    const int p = wid >> 1, half = wid & 1;
    const int r0 = p << 5, base = blockIdx.x * TOK;
    const int row0 = r0 + gid;

    // ---- prologue: FC -> buf0, GRU(0) -> buf1, h_in + x_in half0 (fp16) ----
    stage_async(s_w, g_wp + GW_FC, 5184, t);
    stage_async(s_w + BUF1, g_wp + GW_GRU, 3840, t);
    CP_COMMIT;
    {
        const float4* hsrc = (const float4*)hin;
        for (int i = t; i < TOK * 16; i += TPB) {
            int r = i >> 4, c = i & 15;
            float4 v = hsrc[(size_t)(base + r) * 16 + c];
            *(uint2*)(s_xh + r * XHS + 32 + 2 * c) = make_uint2(h2u(v.x, v.y), h2u(v.z, v.w));
        }
        const float4* xsrc = (const float4*)xin;
        for (int i = t; i < TOK * 16; i += TPB) {
            int r = i >> 4, c = i & 15;
            float4 v = xsrc[(size_t)(base + r) * 32 + c];
            *(uint2*)(s_xh + r * XHS + 2 * c) = make_uint2(h2u(v.x, v.y), h2u(v.z, v.w));
        }
    }
    CP_WAIT0;
    __syncthreads();

    // ---- Stage A: x = relu(x_in @ fc_w^T + b); half1 warps also compute gate ----
    {
        float accF[4][2][4], accG[2][4];
        #pragma unroll
        for (int nt = 0; nt < 4; ++nt) {
            int cb = half * 32 + nt * 8 + 2 * tig;
            float b0 = __ldg(fc_b + cb), b1 = __ldg(fc_b + cb + 1);
            #pragma unroll
            for (int s = 0; s < 2; ++s) {
                accF[nt][s][0] = b0; accF[nt][s][1] = b1;
                accF[nt][s][2] = b0; accF[nt][s][3] = b1;
            }
        }
        {
            float g0 = __ldg(gate_b + 2 * tig), g1 = __ldg(gate_b + 2 * tig + 1);
            #pragma unroll
            for (int s = 0; s < 2; ++s) {
                accG[s][0] = g0; accG[s][1] = g1; accG[s][2] = g0; accG[s][3] = g1;
            }
        }
        #pragma unroll
        for (int kh = 0; kh < 2; ++kh) {
            if (kh == 1) {
                __syncthreads();
                const float4* xsrc = (const float4*)xin;
                for (int i = t; i < TOK * 16; i += TPB) {
                    int r = i >> 4, c = i & 15;
                    float4 v = xsrc[(size_t)(base + r) * 32 + 16 + c];
                    *(uint2*)(s_xh + r * XHS + 2 * c) = make_uint2(h2u(v.x, v.y), h2u(v.z, v.w));
                }
                __syncthreads();
            }
            #pragma unroll
            for (int ks = 0; ks < 4; ++ks) {
                const uint32_t* ap = s_xh + row0 * XHS + ks * 8;
                LOAD_A8(ap)
                const int kb = (kh * 4 + ks) * 8 + 2 * tig;
                #pragma unroll
                for (int nt = 0; nt < 4; ++nt) {
                    uint2 bv = *(const uint2*)(s_w + (half * 32 + nt * 8 + gid) * FCS + kb);
                    MMA2(accF[nt], bv)
                }
                if (half) {
                    uint2 gv = *(const uint2*)(s_w + (64 + gid) * FCS + kb);
                    MMA2(accG, gv)
                }
            }
        }
        PAIR_BAR;   // partner done reading x_in before overwrite
        #pragma unroll
        for (int nt = 0; nt < 4; ++nt) {
            int wq = half * 16 + nt * 4 + tig;
            #pragma unroll
            for (int s = 0; s < 2; ++s) {
                int ra = row0 + s * 16, rb = ra + 8;
                s_xh[ra * XHS + wq] = h2u(fmaxf(accF[nt][s][0], 0.f), fmaxf(accF[nt][s][1], 0.f));
                s_xh[rb * XHS + wq] = h2u(fmaxf(accF[nt][s][2], 0.f), fmaxf(accF[nt][s][3], 0.f));
            }
        }
        if (half) {
            #pragma unroll
            for (int s = 0; s < 2; ++s) {
                int ra = row0 + s * 16, rb = ra + 8;
                s_gate[ra * 9 + 2 * tig]     = sig_(accG[s][0]);
                s_gate[ra * 9 + 2 * tig + 1] = sig_(accG[s][1]);
                s_gate[rb * 9 + 2 * tig]     = sig_(accG[s][2]);
                s_gate[rb * 9 + 2 * tig + 1] = sig_(accG[s][3]);
            }
        }
    }
    __syncthreads();   // stage-A buf0 reads done

    // ---- GRU: 4 chunks, one sync per chunk (ih+hh staged together) ----
    float hpark[24];
    #pragma unroll 1
    for (int c = 0; c < 4; ++c) {
        uint32_t* cur = (c & 1) ? s_w : s_w + BUF1;   // c0 in buf1 (prologue)
        uint32_t* oth = (c & 1) ? s_w + BUF1 : s_w;
        if (c < 3) stage_async(oth, g_wp + GW_GRU + (c + 1) * 3840, 3840, t);
        else       stage_async(oth, g_wp + GW_E, 3840, t);          // E(0) -> buf1
        CP_COMMIT;

        float ar[2][4], az[2][4], ani[2][4], anh[2][4];
        {
            int j0 = c * 16 + half * 8 + 2 * tig;
            float v0 = __ldg(b_ih + j0) + __ldg(b_hh + j0);
            float v1 = __ldg(b_ih + j0 + 1) + __ldg(b_hh + j0 + 1);
            float z0 = __ldg(b_ih + 64 + j0) + __ldg(b_hh + 64 + j0);
            float z1 = __ldg(b_ih + 64 + j0 + 1) + __ldg(b_hh + 64 + j0 + 1);
            float n0 = __ldg(b_ih + 128 + j0), n1 = __ldg(b_ih + 128 + j0 + 1);
            float m0 = __ldg(b_hh + 128 + j0), m1 = __ldg(b_hh + 128 + j0 + 1);
            #pragma unroll
            for (int s = 0; s < 2; ++s) {
                ar[s][0] = v0; ar[s][1] = v1; ar[s][2] = v0; ar[s][3] = v1;
                az[s][0] = z0; az[s][1] = z1; az[s][2] = z0; az[s][3] = z1;
                ani[s][0] = n0; ani[s][1] = n1; ani[s][2] = n0; ani[s][3] = n1;
                anh[s][0] = m0; anh[s][1] = m1; anh[s][2] = m0; anh[s][3] = m1;
            }
        }
        // x-part: A = x (words 0..31), B = ih @ cur
        #pragma unroll
        for (int ks = 0; ks < 4; ++ks) {
            const uint32_t* ap = s_xh + row0 * XHS + ks * 8;
            LOAD_A8(ap)
            const int kb = ks * 8 + 2 * tig;
            uint2 br = *(const uint2*)(cur + (half * 8 + gid) * WS + kb);
            MMA2(ar, br)
            uint2 bz = *(const uint2*)(cur + (16 + half * 8 + gid) * WS + kb);
            MMA2(az, bz)
            uint2 bn = *(const uint2*)(cur + (32 + half * 8 + gid) * WS + kb);
            MMA2(ani, bn)
        }
        // h-part: A = h_in (words 32..63), B = hh @ cur+1920
        #pragma unroll
        for (int ks = 0; ks < 4; ++ks) {
            const uint32_t* ap = s_xh + row0 * XHS + 32 + ks * 8;
            LOAD_A8(ap)
            const int kb = ks * 8 + 2 * tig;
            uint2 br = *(const uint2*)(cur + 1920 + (half * 8 + gid) * WS + kb);
            MMA2(ar, br)
            uint2 bz = *(const uint2*)(cur + 1920 + (16 + half * 8 + gid) * WS + kb);
            MMA2(az, bz)
            uint2 bn = *(const uint2*)(cur + 1920 + (32 + half * 8 + gid) * WS + kb);
            MMA2(anh, bn)
        }
        if (c == 3) { PAIR_BAR; }  // partner finished h_in reads before h writes
        #pragma unroll
        for (int s = 0; s < 2; ++s) {
            #pragma unroll
            for (int rb_ = 0; rb_ < 2; ++rb_) {
                int row = row0 + s * 16 + rb_ * 8;
                int j = c * 16 + half * 8 + 2 * tig;
                int e0 = rb_ * 2;
                float2 hp = u2f2(s_xh[row * XHS + 32 + (j >> 1)]);
                float r0_ = sig_(ar[s][e0]),     r1_ = sig_(ar[s][e0 + 1]);
                float z0_ = sig_(az[s][e0]),     z1_ = sig_(az[s][e0 + 1]);
                float n0_ = tanh_f(fmaf(r0_, anh[s][e0],     ani[s][e0]));
                float n1_ = tanh_f(fmaf(r1_, anh[s][e0 + 1], ani[s][e0 + 1]));
                float h0_ = fmaf(z0_, hp.x - n0_, n0_);
                float h1_ = fmaf(z1_, hp.y - n1_, n1_);
                if (c < 3) { hpark[c * 8 + s * 4 + e0] = h0_; hpark[c * 8 + s * 4 + e0 + 1] = h1_; }
                else s_xh[row * XHS + 32 + (j >> 1)] = h2u(h0_, h1_);
            }
        }
        if (c == 3) {
            #pragma unroll
            for (int cc = 0; cc < 3; ++cc)
                #pragma unroll
                for (int s = 0; s < 2; ++s)
                    #pragma unroll
                    for (int rb_ = 0; rb_ < 2; ++rb_) {
                        int row = row0 + s * 16 + rb_ * 8;
                        int j = cc * 16 + half * 8 + 2 * tig;
                        s_xh[row * XHS + 32 + (j >> 1)] =
                            h2u(hpark[cc * 8 + s * 4 + rb_ * 2],
                                hpark[cc * 8 + s * 4 + rb_ * 2 + 1]);
                    }
        }
        CP_WAIT0;
        __syncthreads();
    }

    // ---- h output (fp16 smem -> f32 gmem, coalesced) ----
    {
        float4* hout = (float4*)(out + (size_t)MTOT * 32);
        for (int i = t; i < TOK * 16; i += TPB) {
            int r = i >> 4, c = i & 15;
            uint2 w2 = *(const uint2*)(s_xh + r * XHS + 32 + 2 * c);
            float2 f0 = u2f2(w2.x), f1 = u2f2(w2.y);
            hout[(size_t)(base + r) * 16 + c] = make_float4(f0.x, f0.y, f1.x, f1.y);
        }
    }

    // ---- experts: E1+E2 staged together; 1 block sync + 1 pair bar per expert ----
    float fq[2][2][4];
    #pragma unroll
    for (int q = 0; q < 2; ++q)
        #pragma unroll
        for (int s = 0; s < 2; ++s)
            { fq[q][s][0] = fq[q][s][1] = fq[q][s][2] = fq[q][s][3] = 0.f; }
    float* eobase = out + (size_t)MTOT * 96;

    #pragma unroll 1
    for (int n = 0; n < 8; ++n) {
        uint32_t* cur = (n & 1) ? s_w : s_w + BUF1;   // E(0) in buf1
        uint32_t* oth = (n & 1) ? s_w + BUF1 : s_w;
        if (n < 7) { stage_async(oth, g_wp + GW_E + (n + 1) * 3840, 3840, t); }
        CP_COMMIT;

        float acc1[4][2][4];
        #pragma unroll
        for (int nt = 0; nt < 4; ++nt) {
            int cb = n * 64 + half * 32 + nt * 8 + 2 * tig;
            float b0 = __ldg(e_b1 + cb), b1 = __ldg(e_b1 + cb + 1);
            #pragma unroll
            for (int s = 0; s < 2; ++s) {
                acc1[nt][s][0] = b0; acc1[nt][s][1] = b1;
                acc1[nt][s][2] = b0; acc1[nt][s][3] = b1;
            }
        }
        // E1: A = h (words 32..63), B @ cur
        #pragma unroll
        for (int ks = 0; ks < 4; ++ks) {
            const uint32_t* ap = s_xh + row0 * XHS + 32 + ks * 8;
            LOAD_A8(ap)
            const int kb = ks * 8 + 2 * tig;
            #pragma unroll
            for (int nt = 0; nt < 4; ++nt) {
                uint2 bv = *(const uint2*)(cur + (half * 32 + nt * 8 + gid) * WS + kb);
                MMA2(acc1[nt], bv)
            }
        }
        #pragma unroll
        for (int nt = 0; nt < 4; ++nt) {   // relu(h1) fp16 -> words 0..31 (pair rows)
            int wq = half * 16 + nt * 4 + tig;
            #pragma unroll
            for (int s = 0; s < 2; ++s) {
                int ra = row0 + s * 16, rb = ra + 8;
                s_xh[ra * XHS + wq] = h2u(fmaxf(acc1[nt][s][0], 0.f), fmaxf(acc1[nt][s][1], 0.f));
                s_xh[rb * XHS + wq] = h2u(fmaxf(acc1[nt][s][2], 0.f), fmaxf(acc1[nt][s][3], 0.f));
            }
        }
        PAIR_BAR;   // pair-local h1 handoff

        float acc2[2][2][4];
        #pragma unroll
        for (int nt = 0; nt < 2; ++nt) {
            int cb = n * 32 + half * 16 + nt * 8 + 2 * tig;
            float b0 = __ldg(e_b2 + cb), b1 = __ldg(e_b2 + cb + 1);
            #pragma unroll
            for (int s = 0; s < 2; ++s) {
                acc2[nt][s][0] = b0; acc2[nt][s][1] = b1;
                acc2[nt][s][2] = b0; acc2[nt][s][3] = b1;
            }
        }
        // E2: A = h1 (words 0..31), B @ cur+2560
        #pragma unroll
        for (int ks = 0; ks < 4; ++ks) {
            const uint32_t* ap = s_xh + row0 * XHS + ks * 8;
            LOAD_A8(ap)
            const int kb = ks * 8 + 2 * tig;
            #pragma unroll
            for (int nt = 0; nt < 2; ++nt) {
                uint2 bv = *(const uint2*)(cur + 2560 + (half * 16 + nt * 8 + gid) * WS + kb);
                MMA2(acc2[nt], bv)
            }
        }
        #pragma unroll
        for (int s = 0; s < 2; ++s) {
            int ra = row0 + s * 16, rb = ra + 8;
            float w0 = s_gate[ra * 9 + n], w1 = s_gate[rb * 9 + n];
            #pragma unroll
            for (int nt = 0; nt < 2; ++nt) {
                fq[nt][s][0] = fmaf(acc2[nt][s][0], w0, fq[nt][s][0]);
                fq[nt][s][1] = fmaf(acc2[nt][s][1], w0, fq[nt][s][1]);
                fq[nt][s][2] = fmaf(acc2[nt][s][2], w1, fq[nt][s][2]);
                fq[nt][s][3] = fmaf(acc2[nt][s][3], w1, fq[nt][s][3]);
                int c0 = n * 32 + half * 16 + nt * 8 + 2 * tig;
                *(float2*)(eobase + (size_t)(base + ra) * 256 + c0) =
                    make_float2(acc2[nt][s][0], acc2[nt][s][1]);
                *(float2*)(eobase + (size_t)(base + rb) * 256 + c0) =
                    make_float2(acc2[nt][s][2], acc2[nt][s][3]);
            }
        }
        CP_WAIT0;
        __syncthreads();   // buffer swap safety
    }

    // ---- final_q ----
    #pragma unroll
    for (int s = 0; s < 2; ++s) {
        int ra = row0 + s * 16, rb = ra + 8;
        #pragma unroll
        for (int nt = 0; nt < 2; ++nt) {
            int c0 = half * 16 + nt * 8 + 2 * tig;
            *(float2*)(out + (size_t)(base + ra) * 32 + c0) =
                make_float2(fq[nt][s][0] * 0.125f, fq[nt][s][1] * 0.125f);
            *(float2*)(out + (size_t)(base + rb) * 32 + c0) =
                make_float2(fq[nt][s][2] * 0.125f, fq[nt][s][3] * 0.125f);
        }
    }
}

extern "C" void kernel_launch(void* const* d_in, const int* in_sizes, int n_in,
                              void* d_out, int out_size) {
    (void)in_sizes; (void)n_in; (void)out_size;
    prep_pack<<<128, 256>>>(
        (const float*)d_in[2],  (const float*)d_in[12],
        (const float*)d_in[4],  (const float*)d_in[5],
        (const float*)d_in[8],  (const float*)d_in[10]);
    cudaFuncSetAttribute(msp_main, cudaFuncAttributeMaxDynamicSharedMemorySize, SMEMW * 4);
    msp_main<<<NBLK, TPB, SMEMW * 4>>>(
        (const float*)d_in[0],  (const float*)d_in[1],
        (const float*)d_in[3],
        (const float*)d_in[6],  (const float*)d_in[7],
        (const float*)d_in[9],  (const float*)d_in[11],
        (const float*)d_in[13],
        (float*)d_out);
}

// round 16
// speedup vs baseline: 1.1403x; 1.0009x over previous
#include <cuda_runtime.h>
#include <cuda_fp16.h>
#include <math.h>
#include <stdint.h>

#define MTOT 131072
#define TPB  128
#define TOK  64
#define NBLK (MTOT / TOK)

// word (uint32/half2) strides
#define XHS 68    // x|h tile row stride in words; %32==4 -> conflict-free scalar A loads
#define WS  40    // K=64 weight row stride in words; %32==8 -> LDS.64 conflict-free
#define FCS 72    // K=128 weight row stride in words

// smem word offsets
#define SW_OFF    0        // buf0 = 5184 words (FC + staged), buf1 = 3840
#define BUF1      5184
#define SXH_OFF   9024     // [64][68]
#define SGATE_OFF 13376    // [64][9] f32
#define SMEMW     13952    // 55,808 B -> 4 CTAs/SM (223.2 KB)

// packed-weight global offsets (words)
#define GW_FC   0          // [72][72] fc(64)+gate(8), K=128
#define GW_GRU  5184       // 4 chunks x 3840 (ih @ +0, hh @ +1920)
#define GW_E    20544      // 8 experts x 3840 (E1 @ +0, E2 @ +2560)
#define GW_TOT  51264

__device__ __align__(16) uint32_t g_wp[GW_TOT];

__device__ __forceinline__ uint32_t h2u(float a, float b) {
    __half2 h = __floats2half2_rn(a, b);
    return *reinterpret_cast<uint32_t*>(&h);
}
__device__ __forceinline__ float2 u2f2(uint32_t u) {
    __half2 h = *reinterpret_cast<__half2*>(&u);
    return __half22float2(h);
}
__device__ __forceinline__ float tanh_f(float v) {
    float y; asm("tanh.approx.f32 %0, %1;" : "=f"(y) : "f"(v)); return y;
}
__device__ __forceinline__ float sig_(float v) {
    return fmaf(tanh_f(0.5f * v), 0.5f, 0.5f);
}
__device__ __forceinline__ int wp_(int w) {
    return ((w >> 3) << 3) + ((w & 3) << 1) + ((w >> 2) & 1);
}

__device__ __forceinline__ void cp16w(uint32_t* dst, const uint32_t* src) {
    uint32_t d = (uint32_t)__cvta_generic_to_shared(dst);
    asm volatile("cp.async.cg.shared.global [%0], [%1], 16;" :: "r"(d), "l"(src));
}
__device__ __forceinline__ void stage_async(uint32_t* dst, const uint32_t* src, int n, int t) {
    for (int i = t * 4; i < n; i += TPB * 4) cp16w(dst + i, src + i);
}
#define CP_COMMIT asm volatile("cp.async.commit_group;")
#define CP_WAIT0  asm volatile("cp.async.wait_group 0;")
#define PAIR_BAR  asm volatile("bar.sync %0, 64;" :: "r"(p + 1) : "memory")

// fp16 m16n8k16, fp32 accumulate
__device__ __forceinline__ void mma16(float* d,
    uint32_t a0, uint32_t a1, uint32_t a2, uint32_t a3, uint32_t b0, uint32_t b1)
{
    asm volatile(
        "mma.sync.aligned.m16n8k16.row.col.f32.f16.f16.f32 "
        "{%0,%1,%2,%3}, {%4,%5,%6,%7}, {%8,%9}, {%0,%1,%2,%3};"
        : "+f"(d[0]), "+f"(d[1]), "+f"(d[2]), "+f"(d[3])
        : "r"(a0), "r"(a1), "r"(a2), "r"(a3), "r"(b0), "r"(b1));
}

#define LOAD_A8(ptr)                              \
    uint32_t a0 = (ptr)[tig];                     \
    uint32_t a2 = (ptr)[tig + 4];                 \
    uint32_t a1 = (ptr)[8 * XHS + tig];           \
    uint32_t a3 = (ptr)[8 * XHS + tig + 4];       \
    uint32_t a4 = (ptr)[16 * XHS + tig];          \
    uint32_t a6 = (ptr)[16 * XHS + tig + 4];      \
    uint32_t a5 = (ptr)[24 * XHS + tig];          \
    uint32_t a7 = (ptr)[24 * XHS + tig + 4];

#define MMA2(acc, bv)                                       \
    mma16((acc)[0], a0, a1, a2, a3, (bv).x, (bv).y);        \
    mma16((acc)[1], a4, a5, a6, a7, (bv).x, (bv).y);

// ---------------- prep: pack + fp16-convert all weights once (wide grid) ----------------
__global__ void __launch_bounds__(256) prep_pack(
    const float* __restrict__ fc_w, const float* __restrict__ gate_w,
    const float* __restrict__ w_ih, const float* __restrict__ w_hh,
    const float* __restrict__ e_w1, const float* __restrict__ e_w2)
{
    int tid = blockIdx.x * blockDim.x + threadIdx.x;
    int nth = gridDim.x * blockDim.x;
    for (int i = tid; i < 72 * 64; i += nth) {        // FC + gate, K=128 (64 words)
        int j = i >> 6, w = i & 63;
        const float* src = (j < 64) ? (fc_w + j * 128) : (gate_w + (j - 64) * 128);
        g_wp[GW_FC + j * FCS + wp_(w)] = h2u(src[2 * w], src[2 * w + 1]);
    }
    for (int i = tid; i < 192 * 32; i += nth) {       // GRU chunks
        int R = i >> 5, w = i & 31;
        int c = (R & 63) >> 4, grp = R >> 6, lr = grp * 16 + (R & 15);
        int d = GW_GRU + c * 3840 + lr * WS + wp_(w);
        g_wp[d]        = h2u(w_ih[R * 64 + 2 * w], w_ih[R * 64 + 2 * w + 1]);
        g_wp[d + 1920] = h2u(w_hh[R * 64 + 2 * w], w_hh[R * 64 + 2 * w + 1]);
    }
    for (int i = tid; i < 8 * 64 * 32; i += nth) {    // E1
        int n = i >> 11, r = (i >> 5) & 63, w = i & 31;
        const float* src = e_w1 + n * 4096 + r * 64;
        g_wp[GW_E + n * 3840 + r * WS + wp_(w)] = h2u(src[2 * w], src[2 * w + 1]);
    }
    for (int i = tid; i < 8 * 32 * 32; i += nth) {    // E2
        int n = i >> 10, r = (i >> 5) & 31, w = i & 31;
        const float* src = e_w2 + n * 2048 + r * 64;
        g_wp[GW_E + n * 3840 + 2560 + r * WS + wp_(w)] = h2u(src[2 * w], src[2 * w + 1]);
    }
}

// ---------------- main: 4 warps (2 pairs), 64 tokens/CTA, 4 CTAs/SM ----------------
__global__ void __launch_bounds__(TPB, 4) msp_main(
    const float* __restrict__ xin,  const float* __restrict__ hin,
    const float* __restrict__ fc_b,
    const float* __restrict__ b_ih, const float* __restrict__ b_hh,
    const float* __restrict__ e_b1, const float* __restrict__ e_b2,
    const float* __restrict__ gate_b,
    float* __restrict__ out)
{
    extern __shared__ uint32_t smw[];
    uint32_t* s_w  = smw + SW_OFF;
    uint32_t* s_xh = smw + SXH_OFF;   // per row: words 0..31 = x/h1, 32..63 = h_in/h
    float* s_gate  = (float*)(smw + SGATE_OFF);

    const int t = threadIdx.x, lane = t & 31, wid = t >> 5;
    const int gid = lane >> 2, tig = lane & 3;
    const int p = wid >> 1, half = wid & 1;
    const int r0 = p << 5, base = blockIdx.x * TOK;
    const int row0 = r0 + gid;

    // ---- prologue: FC -> buf0, GRU(0) -> buf1, h_in + x_in half0 (fp16) ----
    stage_async(s_w, g_wp + GW_FC, 5184, t);
    stage_async(s_w + BUF1, g_wp + GW_GRU, 3840, t);
    CP_COMMIT;
    {
        const float4* hsrc = (const float4*)hin;
        for (int i = t; i < TOK * 16; i += TPB) {
            int r = i >> 4, c = i & 15;
            float4 v = hsrc[(size_t)(base + r) * 16 + c];
            *(uint2*)(s_xh + r * XHS + 32 + 2 * c) = make_uint2(h2u(v.x, v.y), h2u(v.z, v.w));
        }
        const float4* xsrc = (const float4*)xin;
        for (int i = t; i < TOK * 16; i += TPB) {
            int r = i >> 4, c = i & 15;
            float4 v = xsrc[(size_t)(base + r) * 32 + c];
            *(uint2*)(s_xh + r * XHS + 2 * c) = make_uint2(h2u(v.x, v.y), h2u(v.z, v.w));
        }
    }
    CP_WAIT0;
    __syncthreads();

    // ---- Stage A: x = relu(x_in @ fc_w^T + b); half1 warps also compute gate ----
    {
        float accF[4][2][4], accG[2][4];
        #pragma unroll
        for (int nt = 0; nt < 4; ++nt) {
            int cb = half * 32 + nt * 8 + 2 * tig;
            float b0 = __ldg(fc_b + cb), b1 = __ldg(fc_b + cb + 1);
            #pragma unroll
            for (int s = 0; s < 2; ++s) {
                accF[nt][s][0] = b0; accF[nt][s][1] = b1;
                accF[nt][s][2] = b0; accF[nt][s][3] = b1;
            }
        }
        {
            float g0 = __ldg(gate_b + 2 * tig), g1 = __ldg(gate_b + 2 * tig + 1);
            #pragma unroll
            for (int s = 0; s < 2; ++s) {
                accG[s][0] = g0; accG[s][1] = g1; accG[s][2] = g0; accG[s][3] = g1;
            }
        }
        #pragma unroll
        for (int kh = 0; kh < 2; ++kh) {
            if (kh == 1) {
                __syncthreads();
                const float4* xsrc = (const float4*)xin;
                for (int i = t; i < TOK * 16; i += TPB) {
                    int r = i >> 4, c = i & 15;
                    float4 v = xsrc[(size_t)(base + r) * 32 + 16 + c];
                    *(uint2*)(s_xh + r * XHS + 2 * c) = make_uint2(h2u(v.x, v.y), h2u(v.z, v.w));
                }
                __syncthreads();
            }
            #pragma unroll
            for (int ks = 0; ks < 4; ++ks) {
                const uint32_t* ap = s_xh + row0 * XHS + ks * 8;
                LOAD_A8(ap)
                const int kb = (kh * 4 + ks) * 8 + 2 * tig;
                #pragma unroll
                for (int nt = 0; nt < 4; ++nt) {
                    uint2 bv = *(const uint2*)(s_w + (half * 32 + nt * 8 + gid) * FCS + kb);
                    MMA2(accF[nt], bv)
                }
                if (half) {
                    uint2 gv = *(const uint2*)(s_w + (64 + gid) * FCS + kb);
                    MMA2(accG, gv)
                }
            }
        }
        PAIR_BAR;   // partner done reading x_in before overwrite
        #pragma unroll
        for (int nt = 0; nt < 4; ++nt) {
            int wq = half * 16 + nt * 4 + tig;
            #pragma unroll
            for (int s = 0; s < 2; ++s) {
                int ra = row0 + s * 16, rb = ra + 8;
                s_xh[ra * XHS + wq] = h2u(fmaxf(accF[nt][s][0], 0.f), fmaxf(accF[nt][s][1], 0.f));
                s_xh[rb * XHS + wq] = h2u(fmaxf(accF[nt][s][2], 0.f), fmaxf(accF[nt][s][3], 0.f));
            }
        }
        if (half) {
            #pragma unroll
            for (int s = 0; s < 2; ++s) {
                int ra = row0 + s * 16, rb = ra + 8;
                s_gate[ra * 9 + 2 * tig]     = sig_(accG[s][0]);
                s_gate[ra * 9 + 2 * tig + 1] = sig_(accG[s][1]);
                s_gate[rb * 9 + 2 * tig]     = sig_(accG[s][2]);
                s_gate[rb * 9 + 2 * tig + 1] = sig_(accG[s][3]);
            }
        }
    }
    __syncthreads();   // stage-A buf0 reads done

    // ---- GRU: 4 chunks, one sync per chunk (ih+hh staged together) ----
    float hpark[24];
    #pragma unroll 1
    for (int c = 0; c < 4; ++c) {
        uint32_t* cur = (c & 1) ? s_w : s_w + BUF1;   // c0 in buf1 (prologue)
        uint32_t* oth = (c & 1) ? s_w + BUF1 : s_w;
        if (c < 3) stage_async(oth, g_wp + GW_GRU + (c + 1) * 3840, 3840, t);
        else       stage_async(oth, g_wp + GW_E, 3840, t);          // E(0) -> buf1
        CP_COMMIT;

        float ar[2][4], az[2][4], ani[2][4], anh[2][4];
        {
            int j0 = c * 16 + half * 8 + 2 * tig;
            float v0 = __ldg(b_ih + j0) + __ldg(b_hh + j0);
            float v1 = __ldg(b_ih + j0 + 1) + __ldg(b_hh + j0 + 1);
            float z0 = __ldg(b_ih + 64 + j0) + __ldg(b_hh + 64 + j0);
            float z1 = __ldg(b_ih + 64 + j0 + 1) + __ldg(b_hh + 64 + j0 + 1);
            float n0 = __ldg(b_ih + 128 + j0), n1 = __ldg(b_ih + 128 + j0 + 1);
            float m0 = __ldg(b_hh + 128 + j0), m1 = __ldg(b_hh + 128 + j0 + 1);
            #pragma unroll
            for (int s = 0; s < 2; ++s) {
                ar[s][0] = v0; ar[s][1] = v1; ar[s][2] = v0; ar[s][3] = v1;
                az[s][0] = z0; az[s][1] = z1; az[s][2] = z0; az[s][3] = z1;
                ani[s][0] = n0; ani[s][1] = n1; ani[s][2] = n0; ani[s][3] = n1;
                anh[s][0] = m0; anh[s][1] = m1; anh[s][2] = m0; anh[s][3] = m1;
            }
        }
        // x-part: A = x (words 0..31), B = ih @ cur
        #pragma unroll
        for (int ks = 0; ks < 4; ++ks) {
            const uint32_t* ap = s_xh + row0 * XHS + ks * 8;
            LOAD_A8(ap)
            const int kb = ks * 8 + 2 * tig;
            uint2 br = *(const uint2*)(cur + (half * 8 + gid) * WS + kb);
            MMA2(ar, br)
            uint2 bz = *(const uint2*)(cur + (16 + half * 8 + gid) * WS + kb);
            MMA2(az, bz)
            uint2 bn = *(const uint2*)(cur + (32 + half * 8 + gid) * WS + kb);
            MMA2(ani, bn)
        }
        // h-part: A = h_in (words 32..63), B = hh @ cur+1920
        #pragma unroll
        for (int ks = 0; ks < 4; ++ks) {
            const uint32_t* ap = s_xh + row0 * XHS + 32 + ks * 8;
            LOAD_A8(ap)
            const int kb = ks * 8 + 2 * tig;
            uint2 br = *(const uint2*)(cur + 1920 + (half * 8 + gid) * WS + kb);
            MMA2(ar, br)
            uint2 bz = *(const uint2*)(cur + 1920 + (16 + half * 8 + gid) * WS + kb);
            MMA2(az, bz)
            uint2 bn = *(const uint2*)(cur + 1920 + (32 + half * 8 + gid) * WS + kb);
            MMA2(anh, bn)
        }
        if (c == 3) { PAIR_BAR; }  // partner finished h_in reads before h writes
        #pragma unroll
        for (int s = 0; s < 2; ++s) {
            #pragma unroll
            for (int rb_ = 0; rb_ < 2; ++rb_) {
                int row = row0 + s * 16 + rb_ * 8;
                int j = c * 16 + half * 8 + 2 * tig;
                int e0 = rb_ * 2;
                float2 hp = u2f2(s_xh[row * XHS + 32 + (j >> 1)]);
                float r0_ = sig_(ar[s][e0]),     r1_ = sig_(ar[s][e0 + 1]);
                float z0_ = sig_(az[s][e0]),     z1_ = sig_(az[s][e0 + 1]);
                float n0_ = tanh_f(fmaf(r0_, anh[s][e0],     ani[s][e0]));
                float n1_ = tanh_f(fmaf(r1_, anh[s][e0 + 1], ani[s][e0 + 1]));
                float h0_ = fmaf(z0_, hp.x - n0_, n0_);
                float h1_ = fmaf(z1_, hp.y - n1_, n1_);
                if (c < 3) { hpark[c * 8 + s * 4 + e0] = h0_; hpark[c * 8 + s * 4 + e0 + 1] = h1_; }
                else s_xh[row * XHS + 32 + (j >> 1)] = h2u(h0_, h1_);
            }
        }
        if (c == 3) {
            #pragma unroll
            for (int cc = 0; cc < 3; ++cc)
                #pragma unroll
                for (int s = 0; s < 2; ++s)
                    #pragma unroll
                    for (int rb_ = 0; rb_ < 2; ++rb_) {
                        int row = row0 + s * 16 + rb_ * 8;
                        int j = cc * 16 + half * 8 + 2 * tig;
                        s_xh[row * XHS + 32 + (j >> 1)] =
                            h2u(hpark[cc * 8 + s * 4 + rb_ * 2],
                                hpark[cc * 8 + s * 4 + rb_ * 2 + 1]);
                    }
        }
        CP_WAIT0;
        __syncthreads();
    }

    // ---- h output (fp16 smem -> f32 gmem, coalesced) ----
    {
        float4* hout = (float4*)(out + (size_t)MTOT * 32);
        for (int i = t; i < TOK * 16; i += TPB) {
            int r = i >> 4, c = i & 15;
            uint2 w2 = *(const uint2*)(s_xh + r * XHS + 32 + 2 * c);
            float2 f0 = u2f2(w2.x), f1 = u2f2(w2.y);
            hout[(size_t)(base + r) * 16 + c] = make_float4(f0.x, f0.y, f1.x, f1.y);
        }
    }

    // ---- experts: E1+E2 staged together; 1 block sync + 1 pair bar per expert ----
    float fq[2][2][4];
    #pragma unroll
    for (int q = 0; q < 2; ++q)
        #pragma unroll
        for (int s = 0; s < 2; ++s)
            { fq[q][s][0] = fq[q][s][1] = fq[q][s][2] = fq[q][s][3] = 0.f; }
    float* eobase = out + (size_t)MTOT * 96;

    #pragma unroll 1
    for (int n = 0; n < 8; ++n) {
        uint32_t* cur = (n & 1) ? s_w : s_w + BUF1;   // E(0) in buf1
        uint32_t* oth = (n & 1) ? s_w + BUF1 : s_w;
        if (n < 7) { stage_async(oth, g_wp + GW_E + (n + 1) * 3840, 3840, t); CP_COMMIT; }

        float acc1[4][2][4];
        #pragma unroll
        for (int nt = 0; nt < 4; ++nt) {
            int cb = n * 64 + half * 32 + nt * 8 + 2 * tig;
            float b0 = __ldg(e_b1 + cb), b1 = __ldg(e_b1 + cb + 1);
            #pragma unroll
            for (int s = 0; s < 2; ++s) {
                acc1[nt][s][0] = b0; acc1[nt][s][1] = b1;
                acc1[nt][s][2] = b0; acc1[nt][s][3] = b1;
            }
        }
        // E1: A = h (words 32..63), B @ cur
        #pragma unroll
        for (int ks = 0; ks < 4; ++ks) {
            const uint32_t* ap = s_xh + row0 * XHS + 32 + ks * 8;
            LOAD_A8(ap)
            const int kb = ks * 8 + 2 * tig;
            #pragma unroll
            for (int nt = 0; nt < 4; ++nt) {
                uint2 bv = *(const uint2*)(cur + (half * 32 + nt * 8 + gid) * WS + kb);
                MMA2(acc1[nt], bv)
            }
        }
        #pragma unroll
        for (int nt = 0; nt < 4; ++nt) {   // relu(h1) fp16 -> words 0..31 (pair rows)
            int wq = half * 16 + nt * 4 + tig;
            #pragma unroll
            for (int s = 0; s < 2; ++s) {
                int ra = row0 + s * 16, rb = ra + 8;
                s_xh[ra * XHS + wq] = h2u(fmaxf(acc1[nt][s][0], 0.f), fmaxf(acc1[nt][s][1], 0.f));
                s_xh[rb * XHS + wq] = h2u(fmaxf(acc1[nt][s][2], 0.f), fmaxf(acc1[nt][s][3], 0.f));
            }
        }
        PAIR_BAR;   // pair-local h1 handoff

        float acc2[2][2][4];
        #pragma unroll
        for (int nt = 0; nt < 2; ++nt) {
            int cb = n * 32 + half * 16 + nt * 8 + 2 * tig;
            float b0 = __ldg(e_b2 + cb), b1 = __ldg(e_b2 + cb + 1);
            #pragma unroll
            for (int s = 0; s < 2; ++s) {
                acc2[nt][s][0] = b0; acc2[nt][s][1] = b1;
                acc2[nt][s][2] = b0; acc2[nt][s][3] = b1;
            }
        }
        // E2: A = h1 (words 0..31), B @ cur+2560
        #pragma unroll
        for (int ks = 0; ks < 4; ++ks) {
            const uint32_t* ap = s_xh + row0 * XHS + ks * 8;
            LOAD_A8(ap)
            const int kb = ks * 8 + 2 * tig;
            #pragma unroll
            for (int nt = 0; nt < 2; ++nt) {
                uint2 bv = *(const uint2*)(cur + 2560 + (half * 16 + nt * 8 + gid) * WS + kb);
                MMA2(acc2[nt], bv)
            }
        }
        #pragma unroll
        for (int s = 0; s < 2; ++s) {
            int ra = row0 + s * 16, rb = ra + 8;
            float w0 = s_gate[ra * 9 + n], w1 = s_gate[rb * 9 + n];
            #pragma unroll
            for (int nt = 0; nt < 2; ++nt) {
                fq[nt][s][0] = fmaf(acc2[nt][s][0], w0, fq[nt][s][0]);
                fq[nt][s][1] = fmaf(acc2[nt][s][1], w0, fq[nt][s][1]);
                fq[nt][s][2] = fmaf(acc2[nt][s][2], w1, fq[nt][s][2]);
                fq[nt][s][3] = fmaf(acc2[nt][s][3], w1, fq[nt][s][3]);
                int c0 = n * 32 + half * 16 + nt * 8 + 2 * tig;
                *(float2*)(eobase + (size_t)(base + ra) * 256 + c0) =
                    make_float2(acc2[nt][s][0], acc2[nt][s][1]);
                *(float2*)(eobase + (size_t)(base + rb) * 256 + c0) =
                    make_float2(acc2[nt][s][2], acc2[nt][s][3]);
            }
        }
        if (n < 7) {   // last iteration: nothing further reads smem -> skip drain
            CP_WAIT0;
            __syncthreads();
        }
    }

    // ---- final_q (regs -> gmem) ----
    #pragma unroll
    for (int s = 0; s < 2; ++s) {
        int ra = row0 + s * 16, rb = ra + 8;
        #pragma unroll
        for (int nt = 0; nt < 2; ++nt) {
            int c0 = half * 16 + nt * 8 + 2 * tig;
            *(float2*)(out + (size_t)(base + ra) * 32 + c0) =
                make_float2(fq[nt][s][0] * 0.125f, fq[nt][s][1] * 0.125f);
            *(float2*)(out + (size_t)(base + rb) * 32 + c0) =
                make_float2(fq[nt][s][2] * 0.125f, fq[nt][s][3] * 0.125f);
        }
    }
}

extern "C" void kernel_launch(void* const* d_in, const int* in_sizes, int n_in,
                              void* d_out, int out_size) {
    (void)in_sizes; (void)n_in; (void)out_size;
    prep_pack<<<2048, 256>>>(
        (const float*)d_in[2],  (const float*)d_in[12],
        (const float*)d_in[4],  (const float*)d_in[5],
        (const float*)d_in[8],  (const float*)d_in[10]);
    cudaFuncSetAttribute(msp_main, cudaFuncAttributeMaxDynamicSharedMemorySize, SMEMW * 4);
    msp_main<<<NBLK, TPB, SMEMW * 4>>>(
        (const float*)d_in[0],  (const float*)d_in[1],
        (const float*)d_in[3],
        (const float*)d_in[6],  (const float*)d_in[7],
        (const float*)d_in[9],  (const float*)d_in[11],
        (const float*)d_in[13],
        (float*)d_out);
}